// round 12
// baseline (speedup 1.0000x reference)
#include <cuda_runtime.h>
#include <cuda_bf16.h>
#include <math.h>
#include <stdint.h>

#define BB 32
#define NN 1024
#define FF 128
#define RPB 16              // rows per fused block (512 threads)
#define NBLK (NN / RPB)     // 64 partial slabs
#define GC 32
#define CK 32
#define PBLK 128            // prepB blocks per b (8 k-rows each) -> bias slabs

// State: E = exp(y) in [1, e], uint16 fixed-point: 64MB
__device__ unsigned short g_Q[BB * NN * NN];
__device__ float g_colsum[BB * NN];
__device__ float g_part[NBLK * BB * NN];              // 8MB colsum partials
__device__ __nv_bfloat16 g_B[BB * NN * 256];          // 16MB scaled feature [hi|lo]
__device__ float g_biaspart[PBLK * BB * FF];          // 2MB bias partials

// ---------------- fixed-point (magic-number, no cvt pipe) ----------------
#define EMAXR 1.7182837f
#define K1C (EMAXR / 65535.0f)
#define C1C (1.0f - 8388608.0f * K1C)
#define K2C (65535.0f / EMAXR)
#define C2C (8388608.0f - K2C)
#define BCONST (8388608.0f * K1C + C1C)   // effective "1" of the decode

__device__ __forceinline__ float decE(uint32_t u16) {
    return fmaf(__uint_as_float(0x4B000000u | u16), K1C, C1C);
}
__device__ __forceinline__ uint32_t enc2(float a, float b) {
    uint32_t ba = __float_as_uint(fmaf(a, K2C, C2C));
    uint32_t bb = __float_as_uint(fmaf(b, K2C, C2C));
    return (ba & 0xFFFFu) | (bb << 16);
}

// two u16 -> packed bf16x2 of (256*high_byte) and packed bf16x2 of low_byte.
// Bytes <=255 and 256*byte are exact in bf16 -> truncate top 16 bits, no rounding.
__device__ __forceinline__ uint2 cvtA(uint32_t w) {
    uint32_t e0 = w & 0xFFFFu, e1 = w >> 16;
    float h0 = __uint_as_float(0x4B000000u | (e0 >> 8)) - 8388608.0f;
    float l0 = __uint_as_float(0x4B000000u | (e0 & 255u)) - 8388608.0f;
    float h1 = __uint_as_float(0x4B000000u | (e1 >> 8)) - 8388608.0f;
    float l1 = __uint_as_float(0x4B000000u | (e1 & 255u)) - 8388608.0f;
    uint2 r;
    r.x = (__float_as_uint(h0 * 256.0f) >> 16) | (__float_as_uint(h1 * 256.0f) & 0xFFFF0000u);
    r.y = (__float_as_uint(l0) >> 16) | (__float_as_uint(l1) & 0xFFFF0000u);
    return r;
}

// ---------------- PTX helpers ----------------
__device__ __forceinline__ uint32_t smem_u32(const void* p) {
    uint32_t a;
    asm("{ .reg .u64 t; cvta.to.shared.u64 t, %1; cvt.u32.u64 %0, t; }" : "=r"(a) : "l"(p));
    return a;
}
#define CP16(dst, src) asm volatile("cp.async.cg.shared.global [%0], [%1], 16;" :: "r"(dst), "l"(src))
#define CP_COMMIT()    asm volatile("cp.async.commit_group;" ::: "memory")
#define CP_WAIT0()     asm volatile("cp.async.wait_group 0;" ::: "memory")

__device__ __forceinline__ void ldsm_x4(uint32_t* r, uint32_t addr) {
    asm volatile("ldmatrix.sync.aligned.m8n8.x4.shared.b16 {%0,%1,%2,%3}, [%4];"
                 : "=r"(r[0]), "=r"(r[1]), "=r"(r[2]), "=r"(r[3]) : "r"(addr));
}
__device__ __forceinline__ void ldsm_x4_t(uint32_t* r, uint32_t addr) {
    asm volatile("ldmatrix.sync.aligned.m8n8.x4.trans.shared.b16 {%0,%1,%2,%3}, [%4];"
                 : "=r"(r[0]), "=r"(r[1]), "=r"(r[2]), "=r"(r[3]) : "r"(addr));
}
__device__ __forceinline__ void mma_bf16(float* d, const uint32_t* a, const uint32_t* b) {
    asm volatile("mma.sync.aligned.m16n8k16.row.col.f32.bf16.bf16.f32 "
                 "{%0,%1,%2,%3}, {%4,%5,%6,%7}, {%8,%9}, {%0,%1,%2,%3};"
                 : "+f"(d[0]), "+f"(d[1]), "+f"(d[2]), "+f"(d[3])
                 : "r"(a[0]), "r"(a[1]), "r"(a[2]), "r"(a[3]), "r"(b[0]), "r"(b[1]));
}

union PackB4 { __nv_bfloat16 h[4]; uint2 u; };

// ===========================================================================
// Init: row softmax #1; 512 threads, 16 rows (2 row-groups of 8).
// ===========================================================================
__global__ __launch_bounds__(512, 2) void k_init(const float* __restrict__ tmpl,
                                                 const float* __restrict__ uni) {
    const int b = blockIdx.y, t = threadIdx.x;
    const int rh = t >> 8, tc = t & 255, j0 = tc * 4;
    const int rbase = blockIdx.x * RPB + rh * 8;
    __shared__ float part[16][256];
    __shared__ float rred[16];

    float4 x4[8];
#pragma unroll
    for (int rr = 0; rr < 8; rr++) {
        const int row = rbase + rr;
        float4 u = *(const float4*)&uni[((size_t)b * NN + row) * NN + j0];
        float4 tm = *(const float4*)&tmpl[(size_t)row * NN + j0];
        float4 x;
        x.x = (tm.x - __logf(-logf(u.x + 1e-12f) + 1e-12f)) * 5.0f;
        x.y = (tm.y - __logf(-logf(u.y + 1e-12f) + 1e-12f)) * 5.0f;
        x.z = (tm.z - __logf(-logf(u.z + 1e-12f) + 1e-12f)) * 5.0f;
        x.w = (tm.w - __logf(-logf(u.w + 1e-12f) + 1e-12f)) * 5.0f;
        x4[rr] = x;
        part[rh * 8 + rr][tc] = fmaxf(fmaxf(x.x, x.y), fmaxf(x.z, x.w));
    }
    __syncthreads();
    {
        const int w = t >> 5, lane = t & 31;   // 16 warps -> 16 rows
        float v = part[w][lane];
#pragma unroll
        for (int k = 1; k < 8; k++) v = fmaxf(v, part[w][lane + k * 32]);
#pragma unroll
        for (int o = 16; o > 0; o >>= 1) v = fmaxf(v, __shfl_xor_sync(0xffffffffu, v, o));
        if (lane == 0) rred[w] = v;
    }
    __syncthreads();
#pragma unroll
    for (int rr = 0; rr < 8; rr++) {
        const float mx = rred[rh * 8 + rr];
        float4 e;
        e.x = __expf(x4[rr].x - mx);
        e.y = __expf(x4[rr].y - mx);
        e.z = __expf(x4[rr].z - mx);
        e.w = __expf(x4[rr].w - mx);
        x4[rr] = e;
        part[rh * 8 + rr][tc] = (e.x + e.y) + (e.z + e.w);
    }
    __syncthreads();
    {
        const int w = t >> 5, lane = t & 31;
        float v = part[w][lane];
#pragma unroll
        for (int k = 1; k < 8; k++) v += part[w][lane + k * 32];
#pragma unroll
        for (int o = 16; o > 0; o >>= 1) v += __shfl_xor_sync(0xffffffffu, v, o);
        if (lane == 0) rred[w] = 1.0f / v;
    }
    __syncthreads();
    float4 cs = make_float4(0.f, 0.f, 0.f, 0.f);
#pragma unroll
    for (int rr = 0; rr < 8; rr++) {
        const float inv = rred[rh * 8 + rr];
        float Ex = __expf(x4[rr].x * inv);
        float Ey = __expf(x4[rr].y * inv);
        float Ez = __expf(x4[rr].z * inv);
        float Ew = __expf(x4[rr].w * inv);
        uint2 o;
        o.x = enc2(Ex, Ey);
        o.y = enc2(Ez, Ew);
        *(uint2*)&g_Q[((size_t)b * NN + rbase + rr) * NN + j0] = o;
        cs.x += Ex; cs.y += Ey; cs.z += Ez; cs.w += Ew;
    }
    // combine the two row-groups' column partials (reuse part as float4)
    float4* csp = (float4*)part;
    csp[rh * 256 + tc] = cs;
    __syncthreads();
    if (t < 256) {
        float4 a = csp[t], q = csp[256 + t];
        a.x += q.x; a.y += q.y; a.z += q.z; a.w += q.w;
        *(float4*)&g_part[((size_t)blockIdx.x * BB + b) * NN + t * 4] = a;
    }
}

// ===========================================================================
// Reduce 64 partial slabs -> colsum. grid (8, BB), 128 cols/block, MLP 8.
// ===========================================================================
__global__ __launch_bounds__(256) void k_reduce() {
    const int b = blockIdx.y, g = blockIdx.x, t = threadIdx.x;
    const int c = t & 31, p0 = t >> 5;
    const float4* P = (const float4*)g_part;
    float4 s = make_float4(0.f, 0.f, 0.f, 0.f);
#pragma unroll
    for (int p = p0; p < NBLK; p += 8) {
        float4 v = P[((size_t)p * BB + b) * 256 + g * 32 + c];
        s.x += v.x; s.y += v.y; s.z += v.z; s.w += v.w;
    }
    __shared__ float4 sm[8][32];
    sm[p0][c] = s;
    __syncthreads();
    if (t < 32) {
        float4 a = sm[0][t];
#pragma unroll
        for (int p = 1; p < 8; p++) {
            float4 v = sm[p][t];
            a.x += v.x; a.y += v.y; a.z += v.z; a.w += v.w;
        }
        *(float4*)&g_colsum[b * NN + g * 128 + t * 4] = a;
    }
}

// ===========================================================================
// Fused pair (col+row softmax) on u16 state; 512 threads, 16 rows.
// ===========================================================================
__global__ __launch_bounds__(512, 2) void k_fused() {
    const int b = blockIdx.y, t = threadIdx.x;
    const int rh = t >> 8, tc = t & 255, j0 = tc * 4;
    const int rbase = blockIdx.x * RPB + rh * 8;
    __shared__ float part[16][256];
    __shared__ float rinv[16];

    float4 cv = *(const float4*)&g_colsum[b * NN + j0];
    const float4 ic = make_float4(1.0f / cv.x, 1.0f / cv.y, 1.0f / cv.z, 1.0f / cv.w);

    float4 r4[8];
#pragma unroll
    for (int rr = 0; rr < 8; rr++) {
        uint2 w = *(const uint2*)&g_Q[((size_t)b * NN + rbase + rr) * NN + j0];
        float4 r;
        r.x = __expf(decE(w.x & 0xFFFFu) * ic.x);
        r.y = __expf(decE(w.x >> 16) * ic.y);
        r.z = __expf(decE(w.y & 0xFFFFu) * ic.z);
        r.w = __expf(decE(w.y >> 16) * ic.w);
        r4[rr] = r;
        part[rh * 8 + rr][tc] = (r.x + r.y) + (r.z + r.w);
    }
    __syncthreads();
    {
        const int w = t >> 5, lane = t & 31;
        float v = part[w][lane];
#pragma unroll
        for (int k = 1; k < 8; k++) v += part[w][lane + k * 32];
#pragma unroll
        for (int o = 16; o > 0; o >>= 1) v += __shfl_xor_sync(0xffffffffu, v, o);
        if (lane == 0) rinv[w] = 1.0f / v;
    }
    __syncthreads();
    float4 cs = make_float4(0.f, 0.f, 0.f, 0.f);
#pragma unroll
    for (int rr = 0; rr < 8; rr++) {
        const float ir = rinv[rh * 8 + rr];
        float Ex = __expf(r4[rr].x * ir);
        float Ey = __expf(r4[rr].y * ir);
        float Ez = __expf(r4[rr].z * ir);
        float Ew = __expf(r4[rr].w * ir);
        uint2 o;
        o.x = enc2(Ex, Ey);
        o.y = enc2(Ez, Ew);
        *(uint2*)&g_Q[((size_t)b * NN + rbase + rr) * NN + j0] = o;
        cs.x += Ex; cs.y += Ey; cs.z += Ez; cs.w += Ew;
    }
    float4* csp = (float4*)part;
    csp[rh * 256 + tc] = cs;
    __syncthreads();
    if (t < 256) {
        float4 a = csp[t], q = csp[256 + t];
        a.x += q.x; a.y += q.y; a.z += q.z; a.w += q.w;
        *(float4*)&g_part[((size_t)blockIdx.x * BB + b) * NN + t * 4] = a;
    }
}

// ===========================================================================
// prepB: integrated final colsum reduce + B hi/lo build + bias partials.
// grid (128, BB), 256 thr, 8 k-rows per block.
// ===========================================================================
__global__ __launch_bounds__(256) void k_prepB(const float* __restrict__ feat) {
    const int b = blockIdx.y, k0 = blockIdx.x * 8, t = threadIdx.x;
    __shared__ float sm[32][8];
    __shared__ float ics[8];
    __shared__ float4 sb[8][32];
    {
        const int kk = t & 7, p0 = t >> 3;          // 32 p-groups
        float s = 0.f;
#pragma unroll
        for (int p = p0; p < NBLK; p += 32)
            s += g_part[((size_t)p * BB + b) * NN + k0 + kk];
        sm[p0][kk] = s;
        __syncthreads();
        if (t < 8) {
            float a = 0.f;
#pragma unroll
            for (int p = 0; p < 32; p++) a += sm[p][t];
            ics[t] = 1.0f / a;
        }
        __syncthreads();
    }
    const int kg = t >> 5;          // 0..7 local k
    const int k = k0 + kg;
    const int f4 = (t & 31) * 4;
    const float ic = ics[kg];
    float4 v = *(const float4*)&feat[((size_t)b * NN + k) * FF + f4];
    v.x *= ic; v.y *= ic; v.z *= ic; v.w *= ic;
    PackB4 H, L;
    H.h[0] = __float2bfloat16(v.x); L.h[0] = __float2bfloat16(v.x - __bfloat162float(H.h[0]));
    H.h[1] = __float2bfloat16(v.y); L.h[1] = __float2bfloat16(v.y - __bfloat162float(H.h[1]));
    H.h[2] = __float2bfloat16(v.z); L.h[2] = __float2bfloat16(v.z - __bfloat162float(H.h[2]));
    H.h[3] = __float2bfloat16(v.w); L.h[3] = __float2bfloat16(v.w - __bfloat162float(H.h[3]));
    const size_t rb = ((size_t)b * NN + k) * 256;
    *(uint2*)&g_B[rb + f4] = H.u;
    *(uint2*)&g_B[rb + 128 + f4] = L.u;
    // bias partial: sum over this block's 8 k of (H+L)
    float4 bs;
    bs.x = __bfloat162float(H.h[0]) + __bfloat162float(L.h[0]);
    bs.y = __bfloat162float(H.h[1]) + __bfloat162float(L.h[1]);
    bs.z = __bfloat162float(H.h[2]) + __bfloat162float(L.h[2]);
    bs.w = __bfloat162float(H.h[3]) + __bfloat162float(L.h[3]);
    sb[kg][t & 31] = bs;
    __syncthreads();
    if (t < 32) {
        float4 a = sb[0][t];
#pragma unroll
        for (int g = 1; g < 8; g++) {
            float4 w2 = sb[g][t];
            a.x += w2.x; a.y += w2.y; a.z += w2.z; a.w += w2.w;
        }
        ((float4*)g_biaspart)[((size_t)blockIdx.x * BB + b) * 32 + t] = a;
    }
}

// ===========================================================================
// HMMA GEMM from u16 state: out = BCONST*bias + K1C * sum_k u[i][k]*Bs[k][f]
// A split: exact bf16 {256*uh, ul}; B split: {Bh, Bl}; 4 MMA products.
// ===========================================================================
#define ABUF 37888
#define AHI 0
#define ALO 10240
#define BHI 20480
#define BLO_OFF 8704

__global__ __launch_bounds__(256) void k_gemm(float* __restrict__ out) {
    extern __shared__ char smem[];
    __shared__ float biasS[FF];
    __shared__ float4 bred[8][32];
    const int b = blockIdx.y, i0 = blockIdx.x * 128, t = threadIdx.x;
    const int wid = t >> 5, lane = t & 31;
    const int wm = wid & 3, wn = wid >> 2;
    const uint32_t sb = smem_u32(smem);

    // ---- bias reduce (128 slabs) ----
    {
        const float4* BP = (const float4*)g_biaspart;
        const int f4 = t & 31, p0 = t >> 5;
        float4 s = make_float4(0.f, 0.f, 0.f, 0.f);
#pragma unroll
        for (int p = p0; p < PBLK; p += 8) {
            float4 v = BP[((size_t)p * BB + b) * 32 + f4];
            s.x += v.x; s.y += v.y; s.z += v.z; s.w += v.w;
        }
        bred[p0][f4] = s;
        __syncthreads();
        if (t < 32) {
            float4 a = bred[0][t];
#pragma unroll
            for (int p = 1; p < 8; p++) {
                float4 v = bred[p][t];
                a.x += v.x; a.y += v.y; a.z += v.z; a.w += v.w;
            }
            *(float4*)&biasS[t * 4] = a;
        }
    }

    // ---- load slots ----
    const int rowA = t >> 1;
    const char* srcA = (const char*)g_Q +
        (((size_t)b * NN + i0 + rowA) * NN + (size_t)(t & 1) * 16) * 2;
    const uint32_t dAh = sb + AHI + rowA * 80 + (t & 1) * 32;
    const uint32_t dAl = sb + ALO + rowA * 80 + (t & 1) * 32;
    const int rowB = t >> 3, pB = (t & 7) * 64;
    const char* srcB = (const char*)(g_B + (size_t)b * NN * 256) + rowB * 512 + pB;
    const uint32_t dB = sb + BHI + (pB < 256 ? 0 : BLO_OFF) + rowB * 272 + (pB & 255);

    uint4 a0, a1;
#define LDA(cc) do { const uint4* _p = (const uint4*)(srcA + (size_t)(cc) * 64); \
                     a0 = _p[0]; a1 = _p[1]; } while (0)
#define STA(cc) do {                                                     \
        uint2 c0 = cvtA(a0.x), c1 = cvtA(a0.y), c2 = cvtA(a0.z), c3 = cvtA(a0.w); \
        uint2 c4 = cvtA(a1.x), c5 = cvtA(a1.y), c6 = cvtA(a1.z), c7 = cvtA(a1.w); \
        const int _s = (cc) & 1;                                         \
        *(uint4*)(smem + (dAh - sb) + _s * ABUF)      = make_uint4(c0.x, c1.x, c2.x, c3.x); \
        *(uint4*)(smem + (dAh - sb) + _s * ABUF + 16) = make_uint4(c4.x, c5.x, c6.x, c7.x); \
        *(uint4*)(smem + (dAl - sb) + _s * ABUF)      = make_uint4(c0.y, c1.y, c2.y, c3.y); \
        *(uint4*)(smem + (dAl - sb) + _s * ABUF + 16) = make_uint4(c4.y, c5.y, c6.y, c7.y); \
    } while (0)
#define ISSUE_B(cc) do {                                                 \
        const int _s = (cc) & 1;                                         \
        const size_t _bo = (size_t)(cc) * CK * 512;                      \
        CP16(dB + _s * ABUF,      srcB + _bo);                           \
        CP16(dB + _s * ABUF + 16, srcB + _bo + 16);                      \
        CP16(dB + _s * ABUF + 32, srcB + _bo + 32);                      \
        CP16(dB + _s * ABUF + 48, srcB + _bo + 48);                      \
        CP_COMMIT();                                                     \
    } while (0)

    float acc[2][8][4];
#pragma unroll
    for (int mf = 0; mf < 2; mf++)
#pragma unroll
        for (int nf = 0; nf < 8; nf++)
#pragma unroll
            for (int q = 0; q < 4; q++) acc[mf][nf][q] = 0.f;

    LDA(0);
    ISSUE_B(0);
    STA(0);

    for (int c = 0; c < GC; ++c) {
        CP_WAIT0();
        __syncthreads();
        if (c < GC - 1) { LDA(c + 1); ISSUE_B(c + 1); }

        const uint32_t bufA = sb + (c & 1) * ABUF;
#pragma unroll
        for (int ks = 0; ks < 2; ks++) {
            uint32_t aH[2][4], aL[2][4];
#pragma unroll
            for (int mf = 0; mf < 2; mf++) {
                const int r0 = wm * 32 + mf * 16;
                const uint32_t ad = bufA + AHI + (r0 + (lane & 15)) * 80 + ks * 32 + (lane >> 4) * 16;
                ldsm_x4(aH[mf], ad);
                ldsm_x4(aL[mf], ad + (ALO - AHI));
            }
            uint32_t bH[4][4], bL[4][4];
#pragma unroll
            for (int ng = 0; ng < 4; ng++) {
                const int n0 = wn * 64 + ng * 16;
                const uint32_t bd = bufA + BHI + (ks * 16 + (lane & 15)) * 272 + n0 * 2 + (lane >> 4) * 16;
                ldsm_x4_t(bH[ng], bd);
                ldsm_x4_t(bL[ng], bd + BLO_OFF);
            }
#pragma unroll
            for (int mf = 0; mf < 2; mf++)
#pragma unroll
                for (int ng = 0; ng < 4; ng++)
#pragma unroll
                    for (int h = 0; h < 2; h++) {
                        float* d = acc[mf][ng * 2 + h];
                        mma_bf16(d, aH[mf], &bH[ng][h * 2]);
                        mma_bf16(d, aH[mf], &bL[ng][h * 2]);
                        mma_bf16(d, aL[mf], &bH[ng][h * 2]);
                        mma_bf16(d, aL[mf], &bL[ng][h * 2]);
                    }
        }
        if (c < GC - 1) STA(c + 1);
    }

    const int gid = lane >> 2, t4 = lane & 3;
#pragma unroll
    for (int mf = 0; mf < 2; mf++) {
        const int row = i0 + wm * 32 + mf * 16 + gid;
#pragma unroll
        for (int nf = 0; nf < 8; nf++) {
            const int col = wn * 64 + nf * 8 + t4 * 2;
            const float* d = acc[mf][nf];
            float2 o0 = make_float2(fmaf(biasS[col], BCONST, K1C * d[0]),
                                    fmaf(biasS[col + 1], BCONST, K1C * d[1]));
            float2 o1 = make_float2(fmaf(biasS[col], BCONST, K1C * d[2]),
                                    fmaf(biasS[col + 1], BCONST, K1C * d[3]));
            *(float2*)&out[((size_t)b * NN + row) * FF + col] = o0;
            *(float2*)&out[((size_t)b * NN + row + 8) * FF + col] = o1;
        }
    }
}

// ===========================================================================
extern "C" void kernel_launch(void* const* d_in, const int* in_sizes, int n_in,
                              void* d_out, int out_size) {
    const float* feat = (const float*)d_in[0];   // [B,N,F]
    const float* tmpl = (const float*)d_in[1];   // [1,N,N]
    const float* uni  = (const float*)d_in[2];   // [B,N,N]
    float* out = (float*)d_out;                  // [B,N,F]

    cudaFuncSetAttribute(k_gemm, cudaFuncAttributeMaxDynamicSharedMemorySize, 2 * ABUF);

    k_init<<<dim3(NBLK, BB), 512>>>(tmpl, uni);
    k_reduce<<<dim3(8, BB), 256>>>();
    for (int it = 0; it < 8; ++it) {
        k_fused<<<dim3(NBLK, BB), 512>>>();
        k_reduce<<<dim3(8, BB), 256>>>();
    }
    k_fused<<<dim3(NBLK, BB), 512>>>();          // pair #9; partials -> prepB
    k_prepB<<<dim3(PBLK, BB), 256>>>(feat);
    k_gemm<<<dim3(8, BB), 256, 2 * ABUF>>>(out);
}